// round 7
// baseline (speedup 1.0000x reference)
#include <cuda_runtime.h>

// ThresholdEncode: out[i][2t]   = (x[i] <= th_t) && (x[i+1] >  th_t)
//                  out[i][2t+1] = (x[i] >  th_t) && (x[i+1] <= th_t)
// th_t = (t+1)/33, t in [0,32). Last row zeros. Output [n][64] fp32.
//
// At the DRAM-write floor (~6.9 TB/s sustained). This round: exact-fit
// branch-free kernel when total % (256*ITER) == 0 (true for n=1e6):
// 8 front-batched LDGs, no bounds predicates, 4 unconditional STG.128.cs.

#define ITER 4

__global__ void __launch_bounds__(256) ThresholdEncode_exact(
    const float* __restrict__ x, float4* __restrict__ out, int n) {

    const int stride  = gridDim.x * blockDim.x;   // multiple of 16
    const int i0      = blockIdx.x * blockDim.x + threadIdx.x;
    const int nm1     = n - 1;
    const int rowstep = stride >> 4;

    const int   q     = i0 & 15;
    const float inv33 = 1.0f / 33.0f;
    const float th0   = (float)(2 * q + 1) * inv33;
    const float th1   = (float)(2 * q + 2) * inv33;

    const int row0 = i0 >> 4;

    // Front-batched loads: 8 independent LDGs in flight.
    float xp[ITER], xn[ITER];
    #pragma unroll
    for (int k = 0; k < ITER; k++) {
        int r = row0 + k * rowstep;
        xp[k] = __ldg(&x[r]);
        // r+1 == n only for the single last-row chunk; clamp keeps the load
        // in bounds, value unused there (zeroed below).
        xn[k] = __ldg(&x[(r + 1 < n) ? (r + 1) : nm1]);
    }

    #pragma unroll
    for (int k = 0; k < ITER; k++) {
        int r = row0 + k * rowstep;
        float4 v = make_float4(0.f, 0.f, 0.f, 0.f);
        if (r < nm1) {
            bool a0 = (xp[k] <= th0), b0 = (xn[k] > th0);
            bool a1 = (xp[k] <= th1), b1 = (xn[k] > th1);
            v.x = (a0 & b0)   ? 1.0f : 0.0f;
            v.y = (!a0 & !b0) ? 1.0f : 0.0f;
            v.z = (a1 & b1)   ? 1.0f : 0.0f;
            v.w = (!a1 & !b1) ? 1.0f : 0.0f;
        }
        __stcs(&out[i0 + k * stride], v);
    }
}

// General fallback (R6 kernel, bench-best general form).
__global__ void __launch_bounds__(256) ThresholdEncode_general(
    const float* __restrict__ x, float4* __restrict__ out, int n) {

    const int total  = n << 4;
    const int stride = gridDim.x * blockDim.x;
    const int i0     = blockIdx.x * blockDim.x + threadIdx.x;
    const int nm1    = n - 1;

    const int   q     = i0 & 15;
    const float inv33 = 1.0f / 33.0f;
    const float th0   = (float)(2 * q + 1) * inv33;
    const float th1   = (float)(2 * q + 2) * inv33;
    const int rowstep = stride >> 4;

    for (int base = i0; base < total; base += ITER * stride) {
        const int row0 = base >> 4;
        #pragma unroll
        for (int k = 0; k < ITER; k++) {
            int c = base + k * stride;
            if (c < total) {
                int row = row0 + k * rowstep;
                float4 v = make_float4(0.f, 0.f, 0.f, 0.f);
                if (row < nm1) {
                    float xp = __ldg(&x[row]);
                    float xn = __ldg(&x[row + 1]);
                    bool a0 = (xp <= th0), b0 = (xn > th0);
                    bool a1 = (xp <= th1), b1 = (xn > th1);
                    v.x = (a0 & b0)   ? 1.0f : 0.0f;
                    v.y = (!a0 & !b0) ? 1.0f : 0.0f;
                    v.z = (a1 & b1)   ? 1.0f : 0.0f;
                    v.w = (!a1 & !b1) ? 1.0f : 0.0f;
                }
                __stcs(&out[c], v);
            }
        }
    }
}

extern "C" void kernel_launch(void* const* d_in, const int* in_sizes, int n_in,
                              void* d_out, int out_size) {
    const float* x = (const float*)d_in[0];
    float4* out = (float4*)d_out;
    int n = in_sizes[0];

    int total   = n * 16;                        // float4 count
    int threads = 256;
    int chunk   = threads * ITER;                // 1024

    if (total % chunk == 0) {
        int blocks = total / chunk;              // exact fit, loop-free
        ThresholdEncode_exact<<<blocks, threads>>>(x, out, n);
    } else {
        int blocks = (total + chunk - 1) / chunk;
        ThresholdEncode_general<<<blocks, threads>>>(x, out, n);
    }
}